// round 2
// baseline (speedup 1.0000x reference)
#include <cuda_runtime.h>
#include <cstdint>
#include <float.h>
#include <math.h>

#define NB 16384
#define NJ 16384
#define NDIM 128
#define NKF 64
#define N_ELEM (NB * NDIM)
#define N_STAT_BLOCKS 2048
#define JSPLIT 4
#define JCHUNK (NJ / JSPLIT)

// Scratch (device globals; no allocation allowed)
__device__ float g_zf2T[NKF * NB];              // 2*zf folded, [kf][b]  (4 MB)
__device__ float g_znorm[NB];
__device__ float g_eT[NDIM * NJ];               // e transposed [k][j]   (8 MB)
__device__ unsigned long long g_best[NB];       // packed (score,idx)
__device__ float g_partials[N_STAT_BLOCKS * 6];
__device__ float g_colpart[128 * 128];
__device__ float g_colmax;

// ---------------------------------------------------------------------------
// zf2T[kf][b] = fl(z[b,c,h,2w'] + z[b,c,h,2w'+1])  (== 2*zf, exact)
// znorm[b] = 0.5 * sum(zf2^2)  (== sum over 128 dims of zf^2, to ~ulps)
// ---------------------------------------------------------------------------
__global__ void prep_z_kernel(const float* __restrict__ z) {
    int b = blockIdx.x * 128 + threadIdx.x;
    const float* zr = z + (size_t)b * NDIM;
    float sum = 0.f;
#pragma unroll
    for (int kf = 0; kf < NKF; kf++) {
        int c = kf >> 2, h = (kf >> 1) & 1, wp = kf & 1;
        int base = c * 8 + h * 4 + wp * 2;
        float2 p = *reinterpret_cast<const float2*>(zr + base);
        float v = p.x + p.y;
        g_zf2T[kf * NB + b] = v;
        sum = fmaf(v, v, sum);
    }
    g_znorm[b] = 0.5f * sum;
}

// ---------------------------------------------------------------------------
__global__ void transpose_e_kernel(const float* __restrict__ e) {
    int j = blockIdx.x * 256 + threadIdx.x;
    int k4 = blockIdx.y * 4;
    float4 v = *reinterpret_cast<const float4*>(e + (size_t)j * NDIM + k4);
    g_eT[(size_t)(k4 + 0) * NJ + j] = v.x;
    g_eT[(size_t)(k4 + 1) * NJ + j] = v.y;
    g_eT[(size_t)(k4 + 2) * NJ + j] = v.z;
    g_eT[(size_t)(k4 + 3) * NJ + j] = v.w;
}

// ---------------------------------------------------------------------------
__global__ void init_best_kernel() {
    int i = blockIdx.x * 1024 + threadIdx.x;
    g_best[i] = 0xFFFFFFFFFFFFFFFFULL;
}

// ---------------------------------------------------------------------------
// colmax: max over 128 cols of sum_j |e[j,col]|  (two-stage, deterministic)
// ---------------------------------------------------------------------------
__global__ void colmax1_kernel(const float* __restrict__ e) {
    int t = threadIdx.x;
    int r0 = blockIdx.x * 128;
    float s = 0.f;
    for (int r = 0; r < 128; r++)
        s += fabsf(e[(size_t)(r0 + r) * NDIM + t]);
    g_colpart[blockIdx.x * 128 + t] = s;
}
__global__ void colmax2_kernel() {
    __shared__ float sm[128];
    int t = threadIdx.x;
    float s = 0.f;
    for (int bi = 0; bi < 128; bi++) s += g_colpart[bi * 128 + t];
    sm[t] = s;
    __syncthreads();
    for (int off = 64; off > 0; off >>= 1) {
        if (t < off) sm[t] = fmaxf(sm[t], sm[t + off]);
        __syncthreads();
    }
    if (t == 0) g_colmax = sm[0];
}

// ---------------------------------------------------------------------------
// Argmin: replicate d_hat[b][j] = fl( znorm_b - dot_{k=0..127}(2*zf_k, e_jk) )
// with a single fp32 FMA chain per (b,j) in ascending-k order (cublas SGEMM
// order), then argmin with ties -> lowest j.
// Block: 64 rows x 4096 codes (j-split 4). 128 threads, 8x8 per thread.
// ---------------------------------------------------------------------------
__global__ void __launch_bounds__(128, 4) argmin_kernel() {
    __shared__ float zf2_s[NKF][64];   // 16 KB
    __shared__ float e_s[64][128];     // 32 KB (k-chunk of 64)

    int tid = threadIdx.x;
    int tm8 = (tid >> 4) * 8;
    int tn8 = (tid & 15) * 8;
    int row0 = (blockIdx.x >> 2) * 64;
    int jbase = (blockIdx.x & 3) * JCHUNK;

    // stage 2*zf tile (64 folded k-rows x 64 rows)
#pragma unroll
    for (int it = 0; it < 8; it++) {
        int f4 = it * 128 + tid;
        int kf = f4 >> 4;
        int m4 = f4 & 15;
        *reinterpret_cast<float4*>(&zf2_s[kf][m4 * 4]) =
            *reinterpret_cast<const float4*>(&g_zf2T[kf * NB + row0 + m4 * 4]);
    }
    float zn[8];
#pragma unroll
    for (int r = 0; r < 8; r++) zn[r] = g_znorm[row0 + tm8 + r];

    float best[8];
    int bidx[8];
#pragma unroll
    for (int r = 0; r < 8; r++) { best[r] = FLT_MAX; bidx[r] = 0; }

    for (int t = 0; t < JCHUNK / 128; t++) {
        int j0 = jbase + t * 128;
        float acc[8][8];
#pragma unroll
        for (int r = 0; r < 8; r++)
#pragma unroll
            for (int c = 0; c < 8; c++) acc[r][c] = 0.f;

#pragma unroll
        for (int ks = 0; ks < 2; ks++) {
            __syncthreads();
#pragma unroll
            for (int it = 0; it < 16; it++) {
                int f4 = it * 128 + tid;
                int kk = f4 >> 5;
                int n4 = f4 & 31;
                *reinterpret_cast<float4*>(&e_s[kk][n4 * 4]) =
                    *reinterpret_cast<const float4*>(
                        &g_eT[(size_t)(ks * 64 + kk) * NJ + j0 + n4 * 4]);
            }
            __syncthreads();

            // k ascending: k = ks*64 + kk; folded a-row = ks*32 + fold(kk)
#pragma unroll
            for (int kk = 0; kk < 64; kk++) {
                int kf = ks * 32 + ((kk >> 3) << 2) + (kk & 3);
                float4 a0 = *reinterpret_cast<const float4*>(&zf2_s[kf][tm8]);
                float4 a1 = *reinterpret_cast<const float4*>(&zf2_s[kf][tm8 + 4]);
                float4 b0 = *reinterpret_cast<const float4*>(&e_s[kk][tn8]);
                float4 b1 = *reinterpret_cast<const float4*>(&e_s[kk][tn8 + 4]);
                float av[8] = {a0.x, a0.y, a0.z, a0.w, a1.x, a1.y, a1.z, a1.w};
                float bv[8] = {b0.x, b0.y, b0.z, b0.w, b1.x, b1.y, b1.z, b1.w};
#pragma unroll
                for (int r = 0; r < 8; r++)
#pragma unroll
                    for (int c = 0; c < 8; c++)
                        acc[r][c] = fmaf(av[r], bv[c], acc[r][c]);
            }
        }

        // epilogue: score = fl(znorm - dot); strict < keeps lowest j
#pragma unroll
        for (int c = 0; c < 8; c++) {
            int j = j0 + tn8 + c;
#pragma unroll
            for (int r = 0; r < 8; r++) {
                float s = zn[r] - acc[r][c];
                if (s < best[r]) { best[r] = s; bidx[r] = j; }
            }
        }
    }

    // block reduce (pack sortable-score|idx; min => lowest score then lowest j)
    __syncthreads();
    unsigned long long* bs = reinterpret_cast<unsigned long long*>(&e_s[0][0]);
    if (tid < 64) bs[tid] = 0xFFFFFFFFFFFFFFFFULL;
    __syncthreads();
#pragma unroll
    for (int r = 0; r < 8; r++) {
        unsigned u = __float_as_uint(best[r]);
        u = (u & 0x80000000u) ? ~u : (u | 0x80000000u);
        unsigned long long key = ((unsigned long long)u << 32) | (unsigned)bidx[r];
        atomicMin(&bs[tm8 + r], key);
    }
    __syncthreads();
    if (tid < 64) atomicMin(&g_best[row0 + tid], bs[tid]);
}

// ---------------------------------------------------------------------------
// Gather z_q, write transposed output replicating z + fl(z_q - z), stats.
// out[b*128 + w*32 + c*2 + h] = fl(z + fl(q - z)),  q = emb[idx[b], c*8+h*4+w]
// ---------------------------------------------------------------------------
__global__ void gather_stats_kernel(const float* __restrict__ z,
                                    const float* __restrict__ e,
                                    float* __restrict__ outF, int out_size) {
    int t = blockIdx.x * 256 + threadIdx.x;
    int g0 = t * 4;
    int b = g0 >> 7;
    int i0 = g0 & 127;
    int j = (int)(g_best[b] & 0xFFFFFFFFu);
    float4 zv = *reinterpret_cast<const float4*>(z + g0);
    float4 qv = *reinterpret_cast<const float4*>(e + (size_t)j * NDIM + i0);

    float q[4] = {qv.x, qv.y, qv.z, qv.w};
    float zz[4] = {zv.x, zv.y, zv.z, zv.w};
    float d[4], o[4];
#pragma unroll
    for (int u = 0; u < 4; u++) {
        d[u] = __fsub_rn(q[u], zz[u]);     // fl(z_q - z)
        o[u] = __fadd_rn(zz[u], d[u]);     // fl(z + fl(z_q - z))
    }
    int c = i0 >> 3, h = (i0 >> 2) & 1;
    int ob = b * 128 + c * 2 + h;
    outF[ob]      = o[0];
    outF[ob + 32] = o[1];
    outF[ob + 64] = o[2];
    outF[ob + 96] = o[3];
    if (i0 == 0 && out_size >= N_ELEM + 1 + NB)
        outF[N_ELEM + 1 + b] = (float)j;

    float sd2 = 0.f, s1 = 0.f, s2 = 0.f, sxx = 0.f, syy = 0.f, sxy = 0.f;
#pragma unroll
    for (int u = 0; u < 4; u++) {
        sd2 = fmaf(d[u], d[u], sd2);
        s1 += q[u];
        s2 += zz[u];
        sxx = fmaf(q[u], q[u], sxx);
        syy = fmaf(zz[u], zz[u], syy);
        sxy = fmaf(q[u], zz[u], sxy);
    }
#pragma unroll
    for (int off = 16; off; off >>= 1) {
        sd2 += __shfl_down_sync(0xFFFFFFFFu, sd2, off);
        s1  += __shfl_down_sync(0xFFFFFFFFu, s1, off);
        s2  += __shfl_down_sync(0xFFFFFFFFu, s2, off);
        sxx += __shfl_down_sync(0xFFFFFFFFu, sxx, off);
        syy += __shfl_down_sync(0xFFFFFFFFu, syy, off);
        sxy += __shfl_down_sync(0xFFFFFFFFu, sxy, off);
    }
    __shared__ float sm[8][6];
    int wid = threadIdx.x >> 5, lane = threadIdx.x & 31;
    if (lane == 0) {
        sm[wid][0] = sd2; sm[wid][1] = s1; sm[wid][2] = s2;
        sm[wid][3] = sxx; sm[wid][4] = syy; sm[wid][5] = sxy;
    }
    __syncthreads();
    if (threadIdx.x < 6) {
        float a = 0.f;
#pragma unroll
        for (int w = 0; w < 8; w++) a += sm[w][threadIdx.x];
        g_partials[blockIdx.x * 6 + threadIdx.x] = a;
    }
}

// ---------------------------------------------------------------------------
__global__ void final_reduce_kernel(float* __restrict__ outF, int out_size) {
    __shared__ double smr[256];
    __shared__ double tot[6];
    double acc[6] = {0, 0, 0, 0, 0, 0};
    for (int p = threadIdx.x; p < N_STAT_BLOCKS; p += 256) {
#pragma unroll
        for (int s = 0; s < 6; s++) acc[s] += (double)g_partials[p * 6 + s];
    }
    for (int s = 0; s < 6; s++) {
        smr[threadIdx.x] = acc[s];
        __syncthreads();
        for (int off = 128; off > 0; off >>= 1) {
            if (threadIdx.x < off) smr[threadIdx.x] += smr[threadIdx.x + off];
            __syncthreads();
        }
        if (threadIdx.x == 0) tot[s] = smr[0];
        __syncthreads();
    }
    if (threadIdx.x == 0 && out_size >= N_ELEM + 1) {
        double N = (double)N_ELEM;
        double commit = 1.25 * tot[0] / N;
        double cov = tot[5] - tot[1] * tot[2] / N;
        double vx = tot[3] - tot[1] * tot[1] / N;
        double vy = tot[4] - tot[2] * tot[2] / N;
        double pearson = 0.5 + 0.5 * cov / (sqrt(vx) * sqrt(vy));
        double loss = commit + pearson + 0.01 * (double)g_colmax;
        outF[N_ELEM] = (float)loss;
    }
}

// ---------------------------------------------------------------------------
extern "C" void kernel_launch(void* const* d_in, const int* in_sizes, int n_in,
                              void* d_out, int out_size) {
    const float* z = (const float*)d_in[0];
    const float* e = (const float*)d_in[1];
    float* out = (float*)d_out;

    prep_z_kernel<<<NB / 128, 128>>>(z);
    transpose_e_kernel<<<dim3(NJ / 256, 32), 256>>>(e);
    colmax1_kernel<<<128, 128>>>(e);
    colmax2_kernel<<<1, 128>>>();
    init_best_kernel<<<NB / 1024, 1024>>>();
    argmin_kernel<<<(NB / 64) * JSPLIT, 128>>>();
    gather_stats_kernel<<<N_ELEM / 1024, 256>>>(z, e, out, out_size);
    final_reduce_kernel<<<1, 256>>>(out, out_size);
}

// round 3
// speedup vs baseline: 1.4331x; 1.4331x over previous
#include <cuda_runtime.h>
#include <cstdint>
#include <float.h>
#include <math.h>

#define NB 16384
#define NJ 16384
#define NDIM 128
#define NKF 64
#define N_ELEM (NB * NDIM)
#define N_STAT_BLOCKS 2048
#define JSPLIT 16
#define JCHUNK (NJ / JSPLIT)

typedef unsigned long long ull;

// Scratch (device globals; no allocation allowed)
__device__ float g_zf2T[NKF * NB];              // 2*zf folded, [kf][b]  (4 MB)
__device__ float g_znorm[NB];
__device__ float g_eT[NDIM * NJ];               // e transposed [k][j]   (8 MB)
__device__ ull   g_best[NB];                    // packed (score,idx)
__device__ float g_partials[N_STAT_BLOCKS * 6];
__device__ float g_colpart[128 * 128];
__device__ float g_colmax;

// ---------------------------------------------------------------------------
__device__ __forceinline__ uint32_t smem_u32(const void* p) {
    uint32_t r;
    asm("{ .reg .u64 t; cvta.to.shared.u64 t, %1; cvt.u32.u64 %0, t; }"
        : "=r"(r) : "l"(p));
    return r;
}
__device__ __forceinline__ void lds_v2u64(ull& x, ull& y, uint32_t addr) {
    asm volatile("ld.shared.v2.u64 {%0,%1}, [%2];" : "=l"(x), "=l"(y) : "r"(addr));
}
__device__ __forceinline__ void ffma2(ull& d, ull a, ull b) {
    asm("fma.rn.f32x2 %0, %1, %2, %0;" : "+l"(d) : "l"(a), "l"(b));
}
__device__ __forceinline__ void unpack2(float& lo, float& hi, ull v) {
    asm("mov.b64 {%0,%1}, %2;" : "=f"(lo), "=f"(hi) : "l"(v));
}

// ---------------------------------------------------------------------------
// zf2T[kf][b] = fl(z[b,c,h,2w'] + z[b,c,h,2w'+1])  (== 2*zf, exact)
// znorm[b] = 0.5 * sum(zf2^2)
// ---------------------------------------------------------------------------
__global__ void prep_z_kernel(const float* __restrict__ z) {
    int b = blockIdx.x * 128 + threadIdx.x;
    const float* zr = z + (size_t)b * NDIM;
    float sum = 0.f;
#pragma unroll
    for (int kf = 0; kf < NKF; kf++) {
        int c = kf >> 2, h = (kf >> 1) & 1, wp = kf & 1;
        int base = c * 8 + h * 4 + wp * 2;
        float2 p = *reinterpret_cast<const float2*>(zr + base);
        float v = p.x + p.y;
        g_zf2T[kf * NB + b] = v;
        sum = fmaf(v, v, sum);
    }
    g_znorm[b] = 0.5f * sum;
}

// ---------------------------------------------------------------------------
// Tiled transpose: g_eT[k][j] = e[j][k], coalesced both sides.
// ---------------------------------------------------------------------------
__global__ void transpose_e_kernel(const float* __restrict__ e) {
    __shared__ float tile[32 * 129];
    int j0 = blockIdx.x * 32;
    int tid = threadIdx.x;  // 256
#pragma unroll
    for (int it = 0; it < 4; it++) {
        int idx = it * 256 + tid;           // 0..1023 float4
        int jj = idx >> 5;
        int k4 = (idx & 31) * 4;
        float4 v = *reinterpret_cast<const float4*>(&e[(size_t)(j0 + jj) * NDIM + k4]);
        tile[jj * 129 + k4]     = v.x;
        tile[jj * 129 + k4 + 1] = v.y;
        tile[jj * 129 + k4 + 2] = v.z;
        tile[jj * 129 + k4 + 3] = v.w;
    }
    __syncthreads();
#pragma unroll
    for (int it = 0; it < 16; it++) {
        int idx = it * 256 + tid;           // 0..4095
        int k = idx >> 5;
        int jj = idx & 31;
        g_eT[(size_t)k * NJ + j0 + jj] = tile[jj * 129 + k];
    }
}

// ---------------------------------------------------------------------------
__global__ void init_best_kernel() {
    int i = blockIdx.x * 1024 + threadIdx.x;
    g_best[i] = 0xFFFFFFFFFFFFFFFFULL;
}

// ---------------------------------------------------------------------------
__global__ void colmax1_kernel(const float* __restrict__ e) {
    int t = threadIdx.x;
    int r0 = blockIdx.x * 128;
    float s = 0.f;
    for (int r = 0; r < 128; r++)
        s += fabsf(e[(size_t)(r0 + r) * NDIM + t]);
    g_colpart[blockIdx.x * 128 + t] = s;
}
__global__ void colmax2_kernel() {
    __shared__ float sm[128];
    int t = threadIdx.x;
    float s = 0.f;
    for (int bi = 0; bi < 128; bi++) s += g_colpart[bi * 128 + t];
    sm[t] = s;
    __syncthreads();
    for (int off = 64; off > 0; off >>= 1) {
        if (t < off) sm[t] = fmaxf(sm[t], sm[t + off]);
        __syncthreads();
    }
    if (t == 0) g_colmax = sm[0];
}

// ---------------------------------------------------------------------------
// Argmin via packed fp32x2 FMA (FFMA2). Per-lane IEEE-RN, ascending-k chain
// => bitwise identical scores to the scalar version.
// Block: 64 rows x 1024 codes (j-split 16). 128 threads, 8 rows x 8 cols each
// (cols as 4 f32x2 pairs). zf tile stored duplicated so the broadcast operand
// loads as a ready-made {v,v} pair.
// ---------------------------------------------------------------------------
__global__ void __launch_bounds__(128, 3) argmin_kernel() {
    __shared__ float zf_dup[NKF][128];   // 32 KB: [kf][2m]=[kf][2m+1]=zf2[kf][m]
    __shared__ float e_s[32][128];       // 16 KB: 32-k chunk

    int tid = threadIdx.x;
    int tm8 = (tid >> 4) * 8;
    int tn8 = (tid & 15) * 8;
    int row0 = (blockIdx.x & 255) * 64;
    int jbase = (blockIdx.x >> 8) * JCHUNK;

    // stage duplicated 2*zf tile
#pragma unroll
    for (int it = 0; it < 8; it++) {
        int f4 = it * 128 + tid;
        int kf = f4 >> 4, m4 = f4 & 15;
        float4 v = *reinterpret_cast<const float4*>(&g_zf2T[kf * NB + row0 + m4 * 4]);
        *reinterpret_cast<float4*>(&zf_dup[kf][m4 * 8]) =
            make_float4(v.x, v.x, v.y, v.y);
        *reinterpret_cast<float4*>(&zf_dup[kf][m4 * 8 + 4]) =
            make_float4(v.z, v.z, v.w, v.w);
    }
    float zn[8];
#pragma unroll
    for (int r = 0; r < 8; r++) zn[r] = g_znorm[row0 + tm8 + r];

    uint32_t sa_base = smem_u32(zf_dup) + tm8 * 8;
    uint32_t sb_base = smem_u32(e_s) + tn8 * 4;

    float best[8];
    int bidx[8];
#pragma unroll
    for (int r = 0; r < 8; r++) { best[r] = FLT_MAX; bidx[r] = 0; }

    for (int t = 0; t < JCHUNK / 128; t++) {
        int j0 = jbase + t * 128;
        ull acc[8][4];
#pragma unroll
        for (int r = 0; r < 8; r++)
#pragma unroll
            for (int c = 0; c < 4; c++) acc[r][c] = 0ULL;

        const float* ept = g_eT + j0;
        uint32_t sa_ks = sa_base;
        for (int ks = 0; ks < 4; ks++) {   // 32-k chunks, k ascending
            __syncthreads();
#pragma unroll
            for (int it = 0; it < 8; it++) {
                int f4 = it * 128 + tid;
                int kk = f4 >> 5, n4 = f4 & 31;
                *reinterpret_cast<float4*>(&e_s[kk][n4 * 4]) =
                    *reinterpret_cast<const float4*>(&ept[(size_t)kk * NJ + n4 * 4]);
            }
            __syncthreads();

#pragma unroll
            for (int kk = 0; kk < 32; kk++) {
                // global k = ks*32+kk; folded row kf = ks*16 + ((kk>>3)<<2)+(kk&3)
                const int kfo = (((kk >> 3) << 2) + (kk & 3)) * 512;
                ull a0, a1, a2, a3, a4, a5, a6, a7, b0, b1, b2, b3;
                lds_v2u64(a0, a1, sa_ks + kfo);
                lds_v2u64(a2, a3, sa_ks + kfo + 16);
                lds_v2u64(a4, a5, sa_ks + kfo + 32);
                lds_v2u64(a6, a7, sa_ks + kfo + 48);
                lds_v2u64(b0, b1, sb_base + kk * 512);
                lds_v2u64(b2, b3, sb_base + kk * 512 + 16);
                ull av[8] = {a0, a1, a2, a3, a4, a5, a6, a7};
                ull bv[4] = {b0, b1, b2, b3};
#pragma unroll
                for (int r = 0; r < 8; r++)
#pragma unroll
                    for (int c = 0; c < 4; c++)
                        ffma2(acc[r][c], av[r], bv[c]);
            }
            ept += (size_t)32 * NJ;
            sa_ks += 16 * 512;   // 16 kf rows per 32-k chunk
        }

        // epilogue: score = fl(znorm - dot); j ascending, strict < keeps lowest
#pragma unroll
        for (int cp = 0; cp < 4; cp++) {
#pragma unroll
            for (int r = 0; r < 8; r++) {
                float lo, hi;
                unpack2(lo, hi, acc[r][cp]);
                float s0 = zn[r] - lo;
                if (s0 < best[r]) { best[r] = s0; bidx[r] = j0 + tn8 + 2 * cp; }
                float s1 = zn[r] - hi;
                if (s1 < best[r]) { best[r] = s1; bidx[r] = j0 + tn8 + 2 * cp + 1; }
            }
        }
    }

    // block reduce (pack sortable-score|idx; min => lowest score then lowest j)
    __syncthreads();
    ull* bs = reinterpret_cast<ull*>(&e_s[0][0]);
    if (tid < 64) bs[tid] = 0xFFFFFFFFFFFFFFFFULL;
    __syncthreads();
#pragma unroll
    for (int r = 0; r < 8; r++) {
        unsigned u = __float_as_uint(best[r]);
        u = (u & 0x80000000u) ? ~u : (u | 0x80000000u);
        ull key = ((ull)u << 32) | (unsigned)bidx[r];
        atomicMin(&bs[tm8 + r], key);
    }
    __syncthreads();
    if (tid < 64) atomicMin(&g_best[row0 + tid], bs[tid]);
}

// ---------------------------------------------------------------------------
// Gather z_q, write transposed output replicating z + fl(z_q - z), stats.
// ---------------------------------------------------------------------------
__global__ void gather_stats_kernel(const float* __restrict__ z,
                                    const float* __restrict__ e,
                                    float* __restrict__ outF, int out_size) {
    int t = blockIdx.x * 256 + threadIdx.x;
    int g0 = t * 4;
    int b = g0 >> 7;
    int i0 = g0 & 127;
    int j = (int)(g_best[b] & 0xFFFFFFFFu);
    float4 zv = *reinterpret_cast<const float4*>(z + g0);
    float4 qv = *reinterpret_cast<const float4*>(e + (size_t)j * NDIM + i0);

    float q[4] = {qv.x, qv.y, qv.z, qv.w};
    float zz[4] = {zv.x, zv.y, zv.z, zv.w};
    float d[4], o[4];
#pragma unroll
    for (int u = 0; u < 4; u++) {
        d[u] = __fsub_rn(q[u], zz[u]);
        o[u] = __fadd_rn(zz[u], d[u]);
    }
    int c = i0 >> 3, h = (i0 >> 2) & 1;
    int ob = b * 128 + c * 2 + h;
    outF[ob]      = o[0];
    outF[ob + 32] = o[1];
    outF[ob + 64] = o[2];
    outF[ob + 96] = o[3];
    if (i0 == 0 && out_size >= N_ELEM + 1 + NB)
        outF[N_ELEM + 1 + b] = (float)j;

    float sd2 = 0.f, s1 = 0.f, s2 = 0.f, sxx = 0.f, syy = 0.f, sxy = 0.f;
#pragma unroll
    for (int u = 0; u < 4; u++) {
        sd2 = fmaf(d[u], d[u], sd2);
        s1 += q[u];
        s2 += zz[u];
        sxx = fmaf(q[u], q[u], sxx);
        syy = fmaf(zz[u], zz[u], syy);
        sxy = fmaf(q[u], zz[u], sxy);
    }
#pragma unroll
    for (int off = 16; off; off >>= 1) {
        sd2 += __shfl_down_sync(0xFFFFFFFFu, sd2, off);
        s1  += __shfl_down_sync(0xFFFFFFFFu, s1, off);
        s2  += __shfl_down_sync(0xFFFFFFFFu, s2, off);
        sxx += __shfl_down_sync(0xFFFFFFFFu, sxx, off);
        syy += __shfl_down_sync(0xFFFFFFFFu, syy, off);
        sxy += __shfl_down_sync(0xFFFFFFFFu, sxy, off);
    }
    __shared__ float sm[8][6];
    int wid = threadIdx.x >> 5, lane = threadIdx.x & 31;
    if (lane == 0) {
        sm[wid][0] = sd2; sm[wid][1] = s1; sm[wid][2] = s2;
        sm[wid][3] = sxx; sm[wid][4] = syy; sm[wid][5] = sxy;
    }
    __syncthreads();
    if (threadIdx.x < 6) {
        float a = 0.f;
#pragma unroll
        for (int w = 0; w < 8; w++) a += sm[w][threadIdx.x];
        g_partials[blockIdx.x * 6 + threadIdx.x] = a;
    }
}

// ---------------------------------------------------------------------------
__global__ void final_reduce_kernel(float* __restrict__ outF, int out_size) {
    __shared__ double smr[256];
    __shared__ double tot[6];
    double acc[6] = {0, 0, 0, 0, 0, 0};
    for (int p = threadIdx.x; p < N_STAT_BLOCKS; p += 256) {
#pragma unroll
        for (int s = 0; s < 6; s++) acc[s] += (double)g_partials[p * 6 + s];
    }
    for (int s = 0; s < 6; s++) {
        smr[threadIdx.x] = acc[s];
        __syncthreads();
        for (int off = 128; off > 0; off >>= 1) {
            if (threadIdx.x < off) smr[threadIdx.x] += smr[threadIdx.x + off];
            __syncthreads();
        }
        if (threadIdx.x == 0) tot[s] = smr[0];
        __syncthreads();
    }
    if (threadIdx.x == 0 && out_size >= N_ELEM + 1) {
        double N = (double)N_ELEM;
        double commit = 1.25 * tot[0] / N;
        double cov = tot[5] - tot[1] * tot[2] / N;
        double vx = tot[3] - tot[1] * tot[1] / N;
        double vy = tot[4] - tot[2] * tot[2] / N;
        double pearson = 0.5 + 0.5 * cov / (sqrt(vx) * sqrt(vy));
        double loss = commit + pearson + 0.01 * (double)g_colmax;
        outF[N_ELEM] = (float)loss;
    }
}

// ---------------------------------------------------------------------------
extern "C" void kernel_launch(void* const* d_in, const int* in_sizes, int n_in,
                              void* d_out, int out_size) {
    const float* z = (const float*)d_in[0];
    const float* e = (const float*)d_in[1];
    float* out = (float*)d_out;

    prep_z_kernel<<<NB / 128, 128>>>(z);
    transpose_e_kernel<<<NJ / 32, 256>>>(e);
    colmax1_kernel<<<128, 128>>>(e);
    colmax2_kernel<<<1, 128>>>();
    init_best_kernel<<<NB / 1024, 1024>>>();
    argmin_kernel<<<256 * JSPLIT, 128>>>();
    gather_stats_kernel<<<N_ELEM / 1024, 256>>>(z, e, out, out_size);
    final_reduce_kernel<<<1, 256>>>(out, out_size);
}